// round 15
// baseline (speedup 1.0000x reference)
#include <cuda_runtime.h>
#include <cuda_bf16.h>
#include <cstdint>

#define BH      64
#define NH      16
#define NBUCK   32
#define BSZ     128
#define DIM     64
#define TOK     4096
#define ROW     (TOK*DIM)
#define BUCKF   (BSZ*DIM)
#define NCHUNK  4

typedef unsigned long long u64;
typedef uint32_t u32;

__device__ float g_R [BH*NBUCK*NBUCK];
__device__ __align__(16) u32 g_kmh[BH*TOK*32];
__device__ __align__(16) u32 g_kml[BH*TOK*32];

// ---- f32x2 helpers ----------------------------------------------------------
__device__ __forceinline__ u64 pack2(float lo, float hi) {
    u64 r; asm("mov.b64 %0,{%1,%2};" : "=l"(r) : "f"(lo), "f"(hi)); return r;
}
__device__ __forceinline__ u64 dup2(float x) {
    u64 r; asm("mov.b64 %0,{%1,%1};" : "=l"(r) : "f"(x)); return r;
}
__device__ __forceinline__ void fma2(u64 &c, u64 a, u64 b) {
    asm("fma.rn.f32x2 %0,%1,%2,%0;" : "+l"(c) : "l"(a), "l"(b));
}
__device__ __forceinline__ float2 unpk(u64 p) {
    float2 f; asm("mov.b64 {%0,%1},%2;" : "=f"(f.x), "=f"(f.y) : "l"(p)); return f;
}

__device__ __forceinline__ u32 smem_u32(const void* p) {
    u32 a; asm("{ .reg .u64 t; cvta.to.shared.u64 t, %1; cvt.u32.u64 %0, t; }"
               : "=r"(a) : "l"(p)); return a;
}
__device__ __forceinline__ u32 bf2(float a, float b) {
    __nv_bfloat162 h = __floats2bfloat162_rn(a, b);
    return *(u32*)&h;
}
__device__ __forceinline__ void cp_async16(u32 saddr, const void* gaddr) {
    asm volatile("cp.async.cg.shared.global [%0], [%1], 16;"
                 :: "r"(saddr), "l"(gaddr) : "memory");
}
#define CP_COMMIT() asm volatile("cp.async.commit_group;" ::: "memory")
#define CP_WAIT0()  asm volatile("cp.async.wait_group 0;" ::: "memory")

// ---- warp MMA helpers -------------------------------------------------------
__device__ __forceinline__ void mma16816(float c[4], const u32 a[4], const u32* b) {
    asm volatile("mma.sync.aligned.m16n8k16.row.col.f32.bf16.bf16.f32 "
        "{%0,%1,%2,%3},{%4,%5,%6,%7},{%8,%9},{%0,%1,%2,%3};"
        : "+f"(c[0]), "+f"(c[1]), "+f"(c[2]), "+f"(c[3])
        : "r"(a[0]), "r"(a[1]), "r"(a[2]), "r"(a[3]), "r"(b[0]), "r"(b[1]));
}
__device__ __forceinline__ void ldmA(u32 a[4], u32 base, int stride, int lane) {
    int r = lane & 7, q = lane >> 3;
    u32 addr = base + (u32)((r + (q & 1) * 8) * stride + (q >> 1) * 16);
    asm volatile("ldmatrix.sync.aligned.m8n8.x4.shared.b16 {%0,%1,%2,%3}, [%4];"
                 : "=r"(a[0]), "=r"(a[1]), "=r"(a[2]), "=r"(a[3]) : "r"(addr));
}
__device__ __forceinline__ void ldmB(u32 b[4], u32 base, int stride, int lane) {
    int r = lane & 7, q = lane >> 3;
    u32 addr = base + (u32)((r + (q >> 1) * 8) * stride + (q & 1) * 16);
    asm volatile("ldmatrix.sync.aligned.m8n8.x4.shared.b16 {%0,%1,%2,%3}, [%4];"
                 : "=r"(b[0]), "=r"(b[1]), "=r"(b[2]), "=r"(b[3]) : "r"(addr));
}
__device__ __forceinline__ void ldmBt(u32 b[4], u32 base, int stride, int lane) {
    int r = lane & 7, q = lane >> 3;
    u32 addr = base + (u32)((r + (q & 1) * 8) * stride + (q >> 1) * 16);
    asm volatile("ldmatrix.sync.aligned.m8n8.x4.trans.shared.b16 {%0,%1,%2,%3}, [%4];"
                 : "=r"(b[0]), "=r"(b[1]), "=r"(b[2]), "=r"(b[3]) : "r"(addr));
}

// ---------------------------------------------------------------------------
// JAX threefry2x32 (partitionable), key (0,42)
// ---------------------------------------------------------------------------
__device__ __forceinline__ uint32_t rotl32(uint32_t x, int r) {
    return (x << r) | (x >> (32 - r));
}
__device__ __forceinline__ uint32_t jax_bits32(uint32_t n) {
    const uint32_t k0 = 0u, k1 = 42u, k2 = 0u ^ 42u ^ 0x1BD11BDAu;
    uint32_t x0 = k0;
    uint32_t x1 = n + k1;
#define TF_R(r) { x0 += x1; x1 = rotl32(x1, r); x1 ^= x0; }
    TF_R(13) TF_R(15) TF_R(26) TF_R(6)   x0 += k1; x1 += k2 + 1u;
    TF_R(17) TF_R(29) TF_R(16) TF_R(24)  x0 += k2; x1 += k0 + 2u;
    TF_R(13) TF_R(15) TF_R(26) TF_R(6)   x0 += k0; x1 += k1 + 3u;
    TF_R(17) TF_R(29) TF_R(16) TF_R(24)  x0 += k1; x1 += k2 + 4u;
    TF_R(13) TF_R(15) TF_R(26) TF_R(6)   x0 += k2; x1 += k0 + 5u;
#undef TF_R
    return x0 ^ x1;
}

// ---------------------------------------------------------------------------
// K2 (fused): bucket sums (pl) + routing + gumbel + sinkhorn + exp.
// ---------------------------------------------------------------------------
__global__ __launch_bounds__(1024) void k_route_sinkhorn(const float* __restrict__ k,
                                                         const float* __restrict__ Wk) {
    int bh = blockIdx.x;
    int h  = bh & (NH - 1);
    int tid = threadIdx.x;
    int a = tid >> 5, b = tid & 31;

    __shared__ float spl[NBUCK*DIM];
    __shared__ float sW [DIM*NBUCK];
    __shared__ float sT [2][NBUCK*33];

    sW[tid]        = Wk[h*(DIM*NBUCK) + tid];
    sW[tid + 1024] = Wk[h*(DIM*NBUCK) + tid + 1024];

    {
        const float2* kb2 = (const float2*)(k + (size_t)bh*ROW + (size_t)a*BUCKF);
        float sx = 0.f, sy = 0.f;
        #pragma unroll 16
        for (int s = 0; s < BSZ; s++) {
            float2 vv = kb2[s*32 + b];
            sx += vv.x; sy += vv.y;
        }
        spl[a*DIM + 2*b]     = sx;
        spl[a*DIM + 2*b + 1] = sy;
    }
    __syncthreads();

    float r = 0.f;
    #pragma unroll
    for (int d = 0; d < DIM; d++) r += spl[a*DIM + d] * sW[d*NBUCK + b];

    uint32_t n = (uint32_t)(bh*1024 + tid);
    uint32_t bits = jax_bits32(n);
    float u = __uint_as_float((bits >> 9) | 0x3f800000u) - 1.0f;
    float g = -logf(-logf(u + 1e-6f) + 1e-6f);
    r = (r + g) / 0.75f;

    for (int it = 0; it < 5; it++) {
        float m = r;
        #pragma unroll
        for (int o = 16; o >= 1; o >>= 1) m = fmaxf(m, __shfl_xor_sync(0xffffffffu, m, o));
        float s = __expf(r - m);
        #pragma unroll
        for (int o = 16; o >= 1; o >>= 1) s += __shfl_xor_sync(0xffffffffu, s, o);
        r = r - (__logf(s) + m);

        sT[0][b*33 + a] = r;
        __syncthreads();
        r = sT[0][a*33 + b];

        m = r;
        #pragma unroll
        for (int o = 16; o >= 1; o >>= 1) m = fmaxf(m, __shfl_xor_sync(0xffffffffu, m, o));
        s = __expf(r - m);
        #pragma unroll
        for (int o = 16; o >= 1; o >>= 1) s += __shfl_xor_sync(0xffffffffu, s, o);
        r = r - (__logf(s) + m);

        sT[1][b*33 + a] = r;
        __syncthreads();
        r = sT[1][a*33 + b];
    }
    g_R[bh*1024 + tid] = __expf(r);
}

// ---------------------------------------------------------------------------
// K3: Kmix = (R+I) @ K, chunked over bh (bh0 offset).
// ---------------------------------------------------------------------------
__global__ __launch_bounds__(256) void k_kmix(const float* __restrict__ k, int bh0) {
    int bid = blockIdx.x;               // 256 per chunk
    int bh = bh0 + (bid >> 4), c = bid & 15;
    int tid = threadIdx.x;

    __shared__ __align__(16) u64 sAT[NBUCK][18];
    for (int idx = tid; idx < NBUCK*16; idx += 256) {
        int j = idx >> 4, p = idx & 15;
        float a0 = g_R[bh*1024 + (2*p  )*32 + j] + ((2*p   == j) ? 1.0f : 0.0f);
        float a1 = g_R[bh*1024 + (2*p+1)*32 + j] + ((2*p+1 == j) ? 1.0f : 0.0f);
        sAT[j][p] = pack2(a0, a1);
    }
    __syncthreads();

    const float2* kb2 = (const float2*)(k + (size_t)bh*ROW);
    int col2 = c*256 + tid;
    int t = col2 >> 5, dd = col2 & 31;

    u64 ax[16], ay[16];
    #pragma unroll
    for (int p = 0; p < 16; p++) { ax[p] = 0ull; ay[p] = 0ull; }

    #pragma unroll 4
    for (int j = 0; j < NBUCK; j++) {
        float2 kv = kb2[j*4096 + col2];
        u64 vx = dup2(kv.x), vy = dup2(kv.y);
        #pragma unroll
        for (int p4 = 0; p4 < 8; p4++) {
            ulonglong2 aa = *(const ulonglong2*)&sAT[j][2*p4];
            fma2(ax[2*p4],   aa.x, vx);
            fma2(ax[2*p4+1], aa.y, vx);
            fma2(ay[2*p4],   aa.x, vy);
            fma2(ay[2*p4+1], aa.y, vy);
        }
    }

    size_t ob = (size_t)bh * (TOK*32);
    #pragma unroll
    for (int p = 0; p < 16; p++) {
        float2 fx = unpk(ax[p]);
        float2 fy = unpk(ay[p]);
        __nv_bfloat162 h0 = __floats2bfloat162_rn(fx.x, fy.x);
        __nv_bfloat162 l0 = __floats2bfloat162_rn(fx.x - __bfloat162float(h0.x),
                                                  fy.x - __bfloat162float(h0.y));
        size_t o0 = ob + ((size_t)(2*p)*BSZ + t)*32 + dd;
        g_kmh[o0] = *(u32*)&h0;
        g_kml[o0] = *(u32*)&l0;
        __nv_bfloat162 h1 = __floats2bfloat162_rn(fx.y, fy.y);
        __nv_bfloat162 l1 = __floats2bfloat162_rn(fx.y - __bfloat162float(h1.x),
                                                  fy.y - __bfloat162float(h1.y));
        size_t o1 = ob + ((size_t)(2*p+1)*BSZ + t)*32 + dd;
        g_kmh[o1] = *(u32*)&h1;
        g_kml[o1] = *(u32*)&l1;
    }
}

// ---------------------------------------------------------------------------
// K4: bucket attention (round-12 best), chunked over buckets (buck0 offset).
// ---------------------------------------------------------------------------
#define OFF_QH 0
#define OFF_QL 18432
#define OFF_KH 36864
#define OFF_KL 55296
#define OFF_VH 73728
#define OFF_VL 92160
#define OFF_BUFA 0
#define OFF_BUFB 36864
#define OFF_SUM  111616
#define OFF_INV  112640
#define SMEM_TOT 113152
#define SQK 144
#define SV  144
#define SRED 72

__global__ __launch_bounds__(256, 2) void k_attn(const float* __restrict__ q,
                                                 const float* __restrict__ v,
                                                 float* __restrict__ out,
                                                 int buck0) {
    extern __shared__ char smc[];
    u32 sb = smem_u32(smc);
    int tid = threadIdx.x, w = tid >> 5, lane = tid & 31;

    int bid = buck0 + blockIdx.x;
    size_t base = (size_t)bid * BUCKF;
    const float* qb = q + base;
    const float* vb = v + base;

    {
        const uint4* kh16 = (const uint4*)g_kmh + (size_t)bid * 1024;
        const uint4* kl16 = (const uint4*)g_kml + (size_t)bid * 1024;
        for (int i = tid; i < 1024; i += 256) {
            int r = i >> 3, cc = i & 7;
            u32 soff = (u32)(r*SQK + cc*16);
            cp_async16(sb + OFF_KH + soff, kh16 + i);
            cp_async16(sb + OFF_KL + soff, kl16 + i);
        }
        CP_COMMIT();
    }

    for (int i = tid; i < 2048; i += 256) {
        int r = i >> 4, cc = i & 15;
        u32 off = (u32)(r*SQK + cc*8);

        float4 qv = *(const float4*)(qb + r*64 + cc*4);
        qv.x *= 0.125f; qv.y *= 0.125f; qv.z *= 0.125f; qv.w *= 0.125f;
        u32 qh0 = bf2(qv.x, qv.y), qh1 = bf2(qv.z, qv.w);
        __nv_bfloat162 qhh0 = *(__nv_bfloat162*)&qh0;
        __nv_bfloat162 qhh1 = *(__nv_bfloat162*)&qh1;
        u32 ql0 = bf2(qv.x - __bfloat162float(qhh0.x), qv.y - __bfloat162float(qhh0.y));
        u32 ql1 = bf2(qv.z - __bfloat162float(qhh1.x), qv.w - __bfloat162float(qhh1.y));
        *(u64*)(smc + OFF_QH + off) = ((u64)qh1 << 32) | qh0;
        *(u64*)(smc + OFF_QL + off) = ((u64)ql1 << 32) | ql0;

        float4 vv = *(const float4*)(vb + r*64 + cc*4);
        u32 vh0 = bf2(vv.x, vv.y), vh1 = bf2(vv.z, vv.w);
        __nv_bfloat162 vhh0 = *(__nv_bfloat162*)&vh0;
        __nv_bfloat162 vhh1 = *(__nv_bfloat162*)&vh1;
        u32 vl0 = bf2(vv.x - __bfloat162float(vhh0.x), vv.y - __bfloat162float(vhh0.y));
        u32 vl1 = bf2(vv.z - __bfloat162float(vhh1.x), vv.w - __bfloat162float(vhh1.y));
        *(u64*)(smc + OFF_VH + off) = ((u64)vh1 << 32) | vh0;
        *(u64*)(smc + OFF_VL + off) = ((u64)vl1 << 32) | vl0;
    }
    CP_WAIT0();
    __syncthreads();

    int wm = w & 3, wn = w >> 2;
    float acc[2][8][4];
    #pragma unroll
    for (int mt = 0; mt < 2; mt++)
        #pragma unroll
        for (int nt = 0; nt < 8; nt++)
            #pragma unroll
            for (int e = 0; e < 4; e++) acc[mt][nt][e] = 0.f;

    {
        u32 AbH = sb + OFF_QH + wm*32*SQK;
        u32 AbL = sb + OFF_QL + wm*32*SQK;
        u32 BbH = sb + OFF_KH + wn*64*SQK;
        u32 BbL = sb + OFF_KL + wn*64*SQK;
        #pragma unroll
        for (int ks = 0; ks < 4; ks++) {
            u32 ah[2][4], al[2][4], b[4][4];
            ldmA(ah[0], AbH + ks*32,          SQK, lane);
            ldmA(ah[1], AbH + 16*SQK + ks*32, SQK, lane);
            ldmA(al[0], AbL + ks*32,          SQK, lane);
            ldmA(al[1], AbL + 16*SQK + ks*32, SQK, lane);
            #pragma unroll
            for (int np = 0; np < 4; np++)
                ldmB(b[np], BbH + np*16*SQK + ks*32, SQK, lane);
            #pragma unroll
            for (int mt = 0; mt < 2; mt++)
                #pragma unroll
                for (int nt = 0; nt < 8; nt++)
                    mma16816(acc[mt][nt], ah[mt], &b[nt >> 1][(nt & 1)*2]);
            #pragma unroll
            for (int mt = 0; mt < 2; mt++)
                #pragma unroll
                for (int nt = 0; nt < 8; nt++)
                    mma16816(acc[mt][nt], al[mt], &b[nt >> 1][(nt & 1)*2]);
            #pragma unroll
            for (int np = 0; np < 4; np++)
                ldmB(b[np], BbL + np*16*SQK + ks*32, SQK, lane);
            #pragma unroll
            for (int mt = 0; mt < 2; mt++)
                #pragma unroll
                for (int nt = 0; nt < 8; nt++)
                    mma16816(acc[mt][nt], ah[mt], &b[nt >> 1][(nt & 1)*2]);
        }
    }

    float* sSum = (float*)(smc + OFF_SUM);
    float* sInv = (float*)(smc + OFF_INV);
    int g = lane >> 2, qd = lane & 3;

    #pragma unroll
    for (int mt = 0; mt < 2; mt++) {
        int row = wm*32 + mt*16 + g;
        float e0 = 0.f, e1 = 0.f;
        #pragma unroll
        for (int nt = 0; nt < 8; nt++) {
            acc[mt][nt][0] = __expf(acc[mt][nt][0]);
            acc[mt][nt][1] = __expf(acc[mt][nt][1]);
            acc[mt][nt][2] = __expf(acc[mt][nt][2]);
            acc[mt][nt][3] = __expf(acc[mt][nt][3]);
            e0 += acc[mt][nt][0] + acc[mt][nt][1];
            e1 += acc[mt][nt][2] + acc[mt][nt][3];
        }
        e0 += __shfl_xor_sync(0xffffffffu, e0, 1);
        e0 += __shfl_xor_sync(0xffffffffu, e0, 2);
        e1 += __shfl_xor_sync(0xffffffffu, e1, 1);
        e1 += __shfl_xor_sync(0xffffffffu, e1, 2);
        if (qd == 0) {
            sSum[wn*128 + row]     = e0;
            sSum[wn*128 + row + 8] = e1;
        }
    }
    __syncthreads();

    if (wn == 0 && qd == 0) {
        #pragma unroll
        for (int mt = 0; mt < 2; mt++) {
            int row = wm*32 + mt*16 + g;
            sInv[row]     = 1.0f / (sSum[row]     + sSum[128 + row]);
            sInv[row + 8] = 1.0f / (sSum[row + 8] + sSum[128 + row + 8]);
        }
    }

    u32 AH[2][4][4], AL[2][4][4];
    #pragma unroll
    for (int mt = 0; mt < 2; mt++)
        #pragma unroll
        for (int t = 0; t < 4; t++) {
            #pragma unroll
            for (int hp = 0; hp < 2; hp++) {
                float p0 = acc[mt][2*t+hp][0], p1 = acc[mt][2*t+hp][1];
                float p2 = acc[mt][2*t+hp][2], p3 = acc[mt][2*t+hp][3];
                u32 h01 = bf2(p0, p1), h23 = bf2(p2, p3);
                __nv_bfloat162 hh01 = *(__nv_bfloat162*)&h01;
                __nv_bfloat162 hh23 = *(__nv_bfloat162*)&h23;
                AH[mt][t][2*hp]   = h01;
                AH[mt][t][2*hp+1] = h23;
                AL[mt][t][2*hp]   = bf2(p0 - __bfloat162float(hh01.x),
                                        p1 - __bfloat162float(hh01.y));
                AL[mt][t][2*hp+1] = bf2(p2 - __bfloat162float(hh23.x),
                                        p3 - __bfloat162float(hh23.y));
            }
        }

    u32 bufoff = (wn == 0) ? OFF_BUFA : OFF_BUFB;
    #pragma unroll
    for (int half = 0; half < 2; half++) {
        float o[2][4][4];
        #pragma unroll
        for (int mt = 0; mt < 2; mt++)
            #pragma unroll
            for (int nt = 0; nt < 4; nt++)
                #pragma unroll
                for (int e = 0; e < 4; e++) o[mt][nt][e] = 0.f;

        #pragma unroll
        for (int t = 0; t < 4; t++) {
            u32 vrow = sb + OFF_VH + (wn*64 + t*16)*SV + half*64;
            u32 b[2][4];
            ldmBt(b[0], vrow,      SV, lane);
            ldmBt(b[1], vrow + 32, SV, lane);
            #pragma unroll
            for (int mt = 0; mt < 2; mt++)
                #pragma unroll
                for (int nt = 0; nt < 4; nt++)
                    mma16816(o[mt][nt], AH[mt][t], &b[nt >> 1][(nt & 1)*2]);
            #pragma unroll
            for (int mt = 0; mt < 2; mt++)
                #pragma unroll
                for (int nt = 0; nt < 4; nt++)
                    mma16816(o[mt][nt], AL[mt][t], &b[nt >> 1][(nt & 1)*2]);
            u32 vrl = vrow + (OFF_VL - OFF_VH);
            ldmBt(b[0], vrl,      SV, lane);
            ldmBt(b[1], vrl + 32, SV, lane);
            #pragma unroll
            for (int mt = 0; mt < 2; mt++)
                #pragma unroll
                for (int nt = 0; nt < 4; nt++)
                    mma16816(o[mt][nt], AH[mt][t], &b[nt >> 1][(nt & 1)*2]);
        }

        #pragma unroll
        for (int mt = 0; mt < 2; mt++) {
            int row0 = wm*32 + mt*16 + g;
            #pragma unroll
            for (int nt = 0; nt < 4; nt++) {
                u32 cb = (u32)((half*32 + nt*8 + qd*2) * 4);
                *(float2*)(smc + bufoff + row0*(SRED*4) + cb) =
                    make_float2(o[mt][nt][0], o[mt][nt][1]);
                *(float2*)(smc + bufoff + (row0+8)*(SRED*4) + cb) =
                    make_float2(o[mt][nt][2], o[mt][nt][3]);
            }
        }
    }
    __syncthreads();

    const float* bA = (const float*)(smc + OFF_BUFA);
    const float* bB = (const float*)(smc + OFF_BUFB);
    float* ob = out + base;
    for (int i = tid; i < 2048; i += 256) {
        int r = i >> 4, c4 = i & 15;
        float4 a4 = *(const float4*)(bA + r*SRED + c4*4);
        float4 b4 = *(const float4*)(bB + r*SRED + c4*4);
        float inv = sInv[r];
        float4 res = make_float4((a4.x + b4.x)*inv, (a4.y + b4.y)*inv,
                                 (a4.z + b4.z)*inv, (a4.w + b4.w)*inv);
        *(float4*)(ob + r*64 + c4*4) = res;
    }
}

// ---------------------------------------------------------------------------
// Launch: fork/join pipeline — kmix chunk c (main stream) gates attn chunk c
// (side stream). Stream/events created once on the (non-captured) first call.
// ---------------------------------------------------------------------------
extern "C" void kernel_launch(void* const* d_in, const int* in_sizes, int n_in,
                              void* d_out, int out_size) {
    const float* q  = (const float*)d_in[0];
    const float* k  = (const float*)d_in[1];
    const float* v  = (const float*)d_in[2];
    const float* Wk = (const float*)d_in[3];
    float* out = (float*)d_out;

    static cudaStream_t s2 = nullptr;
    static cudaEvent_t evK[NCHUNK], evDone;
    if (s2 == nullptr) {
        cudaStreamCreateWithFlags(&s2, cudaStreamNonBlocking);
        for (int i = 0; i < NCHUNK; i++)
            cudaEventCreateWithFlags(&evK[i], cudaEventDisableTiming);
        cudaEventCreateWithFlags(&evDone, cudaEventDisableTiming);
        cudaFuncSetAttribute(k_attn, cudaFuncAttributeMaxDynamicSharedMemorySize, SMEM_TOT);
    }

    k_route_sinkhorn<<<BH, 1024>>>(k, Wk);

    for (int c = 0; c < NCHUNK; c++) {
        k_kmix<<<(BH/NCHUNK)*16, 256>>>(k, c*(BH/NCHUNK));
        cudaEventRecord(evK[c], 0);
    }
    for (int c = 0; c < NCHUNK; c++) {
        cudaStreamWaitEvent(s2, evK[c], 0);
        k_attn<<<(BH/NCHUNK)*NBUCK, 256, SMEM_TOT, s2>>>(q, v, out, c*(BH/NCHUNK)*NBUCK);
    }
    cudaEventRecord(evDone, s2);
    cudaStreamWaitEvent(0, evDone, 0);
}

// round 16
// speedup vs baseline: 1.0419x; 1.0419x over previous
#include <cuda_runtime.h>
#include <cuda_bf16.h>
#include <cstdint>

#define BH      64
#define NH      16
#define NBUCK   32
#define BSZ     128
#define DIM     64
#define TOK     4096
#define ROW     (TOK*DIM)
#define BUCKF   (BSZ*DIM)

typedef unsigned long long u64;
typedef uint32_t u32;

__device__ float g_R [BH*NBUCK*NBUCK];
__device__ __align__(16) u32 g_kmh[BH*TOK*32];
__device__ __align__(16) u32 g_kml[BH*TOK*32];

// ---- f32x2 helpers ----------------------------------------------------------
__device__ __forceinline__ u64 pack2(float lo, float hi) {
    u64 r; asm("mov.b64 %0,{%1,%2};" : "=l"(r) : "f"(lo), "f"(hi)); return r;
}
__device__ __forceinline__ u64 dup2(float x) {
    u64 r; asm("mov.b64 %0,{%1,%1};" : "=l"(r) : "f"(x)); return r;
}
__device__ __forceinline__ void fma2(u64 &c, u64 a, u64 b) {
    asm("fma.rn.f32x2 %0,%1,%2,%0;" : "+l"(c) : "l"(a), "l"(b));
}
__device__ __forceinline__ float2 unpk(u64 p) {
    float2 f; asm("mov.b64 {%0,%1},%2;" : "=f"(f.x), "=f"(f.y) : "l"(p)); return f;
}

__device__ __forceinline__ u32 smem_u32(const void* p) {
    u32 a; asm("{ .reg .u64 t; cvta.to.shared.u64 t, %1; cvt.u32.u64 %0, t; }"
               : "=r"(a) : "l"(p)); return a;
}
__device__ __forceinline__ u32 bf2(float a, float b) {
    __nv_bfloat162 h = __floats2bfloat162_rn(a, b);
    return *(u32*)&h;
}
__device__ __forceinline__ void cp_async16(u32 saddr, const void* gaddr) {
    asm volatile("cp.async.cg.shared.global [%0], [%1], 16;"
                 :: "r"(saddr), "l"(gaddr) : "memory");
}
#define CP_COMMIT() asm volatile("cp.async.commit_group;" ::: "memory")
#define CP_WAIT0()  asm volatile("cp.async.wait_group 0;" ::: "memory")

// ---- warp MMA helpers -------------------------------------------------------
__device__ __forceinline__ void mma16816(float c[4], const u32 a[4], const u32* b) {
    asm volatile("mma.sync.aligned.m16n8k16.row.col.f32.bf16.bf16.f32 "
        "{%0,%1,%2,%3},{%4,%5,%6,%7},{%8,%9},{%0,%1,%2,%3};"
        : "+f"(c[0]), "+f"(c[1]), "+f"(c[2]), "+f"(c[3])
        : "r"(a[0]), "r"(a[1]), "r"(a[2]), "r"(a[3]), "r"(b[0]), "r"(b[1]));
}
__device__ __forceinline__ void ldmA(u32 a[4], u32 base, int stride, int lane) {
    int r = lane & 7, q = lane >> 3;
    u32 addr = base + (u32)((r + (q & 1) * 8) * stride + (q >> 1) * 16);
    asm volatile("ldmatrix.sync.aligned.m8n8.x4.shared.b16 {%0,%1,%2,%3}, [%4];"
                 : "=r"(a[0]), "=r"(a[1]), "=r"(a[2]), "=r"(a[3]) : "r"(addr));
}
__device__ __forceinline__ void ldmB(u32 b[4], u32 base, int stride, int lane) {
    int r = lane & 7, q = lane >> 3;
    u32 addr = base + (u32)((r + (q >> 1) * 8) * stride + (q & 1) * 16);
    asm volatile("ldmatrix.sync.aligned.m8n8.x4.shared.b16 {%0,%1,%2,%3}, [%4];"
                 : "=r"(b[0]), "=r"(b[1]), "=r"(b[2]), "=r"(b[3]) : "r"(addr));
}
__device__ __forceinline__ void ldmBt(u32 b[4], u32 base, int stride, int lane) {
    int r = lane & 7, q = lane >> 3;
    u32 addr = base + (u32)((r + (q & 1) * 8) * stride + (q >> 1) * 16);
    asm volatile("ldmatrix.sync.aligned.m8n8.x4.trans.shared.b16 {%0,%1,%2,%3}, [%4];"
                 : "=r"(b[0]), "=r"(b[1]), "=r"(b[2]), "=r"(b[3]) : "r"(addr));
}

// ---------------------------------------------------------------------------
// JAX threefry2x32 (partitionable), key (0,42)
// ---------------------------------------------------------------------------
__device__ __forceinline__ uint32_t rotl32(uint32_t x, int r) {
    return (x << r) | (x >> (32 - r));
}
__device__ __forceinline__ uint32_t jax_bits32(uint32_t n) {
    const uint32_t k0 = 0u, k1 = 42u, k2 = 0u ^ 42u ^ 0x1BD11BDAu;
    uint32_t x0 = k0;
    uint32_t x1 = n + k1;
#define TF_R(r) { x0 += x1; x1 = rotl32(x1, r); x1 ^= x0; }
    TF_R(13) TF_R(15) TF_R(26) TF_R(6)   x0 += k1; x1 += k2 + 1u;
    TF_R(17) TF_R(29) TF_R(16) TF_R(24)  x0 += k2; x1 += k0 + 2u;
    TF_R(13) TF_R(15) TF_R(26) TF_R(6)   x0 += k0; x1 += k1 + 3u;
    TF_R(17) TF_R(29) TF_R(16) TF_R(24)  x0 += k1; x1 += k2 + 4u;
    TF_R(13) TF_R(15) TF_R(26) TF_R(6)   x0 += k2; x1 += k0 + 5u;
#undef TF_R
    return x0 ^ x1;
}

// ---------------------------------------------------------------------------
// K2 (fused): bucket sums (pl) + routing + gumbel + sinkhorn + exp.
// ---------------------------------------------------------------------------
__global__ __launch_bounds__(1024) void k_route_sinkhorn(const float* __restrict__ k,
                                                         const float* __restrict__ Wk) {
    int bh = blockIdx.x;
    int h  = bh & (NH - 1);
    int tid = threadIdx.x;
    int a = tid >> 5, b = tid & 31;

    __shared__ float spl[NBUCK*DIM];
    __shared__ float sW [DIM*NBUCK];
    __shared__ float sT [2][NBUCK*33];

    sW[tid]        = Wk[h*(DIM*NBUCK) + tid];
    sW[tid + 1024] = Wk[h*(DIM*NBUCK) + tid + 1024];

    {
        const float2* kb2 = (const float2*)(k + (size_t)bh*ROW + (size_t)a*BUCKF);
        float sx = 0.f, sy = 0.f;
        #pragma unroll 16
        for (int s = 0; s < BSZ; s++) {
            float2 vv = kb2[s*32 + b];
            sx += vv.x; sy += vv.y;
        }
        spl[a*DIM + 2*b]     = sx;
        spl[a*DIM + 2*b + 1] = sy;
    }
    __syncthreads();

    float r = 0.f;
    #pragma unroll
    for (int d = 0; d < DIM; d++) r += spl[a*DIM + d] * sW[d*NBUCK + b];

    uint32_t n = (uint32_t)(bh*1024 + tid);
    uint32_t bits = jax_bits32(n);
    float u = __uint_as_float((bits >> 9) | 0x3f800000u) - 1.0f;
    float g = -logf(-logf(u + 1e-6f) + 1e-6f);
    r = (r + g) / 0.75f;

    for (int it = 0; it < 5; it++) {
        float m = r;
        #pragma unroll
        for (int o = 16; o >= 1; o >>= 1) m = fmaxf(m, __shfl_xor_sync(0xffffffffu, m, o));
        float s = __expf(r - m);
        #pragma unroll
        for (int o = 16; o >= 1; o >>= 1) s += __shfl_xor_sync(0xffffffffu, s, o);
        r = r - (__logf(s) + m);

        sT[0][b*33 + a] = r;
        __syncthreads();
        r = sT[0][a*33 + b];

        m = r;
        #pragma unroll
        for (int o = 16; o >= 1; o >>= 1) m = fmaxf(m, __shfl_xor_sync(0xffffffffu, m, o));
        s = __expf(r - m);
        #pragma unroll
        for (int o = 16; o >= 1; o >>= 1) s += __shfl_xor_sync(0xffffffffu, s, o);
        r = r - (__logf(s) + m);

        sT[1][b*33 + a] = r;
        __syncthreads();
        r = sT[1][a*33 + b];
    }
    g_R[bh*1024 + tid] = __expf(r);
}

// ---------------------------------------------------------------------------
// K3: Kmix = (R+I) @ K — row-split: each CTA computes 16 bucket-rows for its
// 256-float2 column chunk (accs 16 u64 = half the register pressure).
// grid = BH * 32  (bh, rh in {0,1}, col chunk c in 0..15), 256 threads.
// K is read twice chip-wide (L2/DRAM headroom available); latency bound fixed.
// ---------------------------------------------------------------------------
__global__ __launch_bounds__(256) void k_kmix(const float* __restrict__ k) {
    int bid = blockIdx.x;               // 2048
    int bh = bid >> 5, rh = (bid >> 4) & 1, c = bid & 15;
    int row0 = rh * 16;                 // first of 16 owned bucket-rows

    int tid = threadIdx.x;

    __shared__ __align__(16) u64 sAT[NBUCK][10];   // [j][p]: rows (row0+2p, +1), p<8
    for (int idx = tid; idx < NBUCK*8; idx += 256) {
        int j = idx >> 3, p = idx & 7;
        int r0 = row0 + 2*p, r1 = r0 + 1;
        float a0 = g_R[bh*1024 + r0*32 + j] + ((r0 == j) ? 1.0f : 0.0f);
        float a1 = g_R[bh*1024 + r1*32 + j] + ((r1 == j) ? 1.0f : 0.0f);
        sAT[j][p] = pack2(a0, a1);
    }
    __syncthreads();

    const float2* kb2 = (const float2*)(k + (size_t)bh*ROW);
    int col2 = c*256 + tid;
    int t = col2 >> 5, dd = col2 & 31;

    u64 ax[8], ay[8];
    #pragma unroll
    for (int p = 0; p < 8; p++) { ax[p] = 0ull; ay[p] = 0ull; }

    #pragma unroll 4
    for (int j = 0; j < NBUCK; j++) {
        float2 kv = kb2[j*4096 + col2];
        u64 vx = dup2(kv.x), vy = dup2(kv.y);
        #pragma unroll
        for (int p4 = 0; p4 < 4; p4++) {
            ulonglong2 aa = *(const ulonglong2*)&sAT[j][2*p4];
            fma2(ax[2*p4],   aa.x, vx);
            fma2(ax[2*p4+1], aa.y, vx);
            fma2(ay[2*p4],   aa.x, vy);
            fma2(ay[2*p4+1], aa.y, vy);
        }
    }

    size_t ob = (size_t)bh * (TOK*32);
    #pragma unroll
    for (int p = 0; p < 8; p++) {
        float2 fx = unpk(ax[p]);
        float2 fy = unpk(ay[p]);
        int r0 = row0 + 2*p, r1 = r0 + 1;
        __nv_bfloat162 h0 = __floats2bfloat162_rn(fx.x, fy.x);
        __nv_bfloat162 l0 = __floats2bfloat162_rn(fx.x - __bfloat162float(h0.x),
                                                  fy.x - __bfloat162float(h0.y));
        size_t o0 = ob + ((size_t)r0*BSZ + t)*32 + dd;
        g_kmh[o0] = *(u32*)&h0;
        g_kml[o0] = *(u32*)&l0;
        __nv_bfloat162 h1 = __floats2bfloat162_rn(fx.y, fy.y);
        __nv_bfloat162 l1 = __floats2bfloat162_rn(fx.y - __bfloat162float(h1.x),
                                                  fy.y - __bfloat162float(h1.y));
        size_t o1 = ob + ((size_t)r1*BSZ + t)*32 + dd;
        g_kmh[o1] = *(u32*)&h1;
        g_kml[o1] = *(u32*)&l1;
    }
}

// ---------------------------------------------------------------------------
// K4: bucket attention — round-12 best (register-P GEMM2, sInv precompute).
// ---------------------------------------------------------------------------
#define OFF_QH 0
#define OFF_QL 18432
#define OFF_KH 36864
#define OFF_KL 55296
#define OFF_VH 73728
#define OFF_VL 92160
#define OFF_BUFA 0
#define OFF_BUFB 36864
#define OFF_SUM  111616
#define OFF_INV  112640
#define SMEM_TOT 113152
#define SQK 144
#define SV  144
#define SRED 72

__global__ __launch_bounds__(256, 2) void k_attn(const float* __restrict__ q,
                                                 const float* __restrict__ v,
                                                 float* __restrict__ out) {
    extern __shared__ char smc[];
    u32 sb = smem_u32(smc);
    int tid = threadIdx.x, w = tid >> 5, lane = tid & 31;

    size_t base = (size_t)blockIdx.x * BUCKF;
    const float* qb = q + base;
    const float* vb = v + base;

    {
        const uint4* kh16 = (const uint4*)g_kmh + (size_t)blockIdx.x * 1024;
        const uint4* kl16 = (const uint4*)g_kml + (size_t)blockIdx.x * 1024;
        for (int i = tid; i < 1024; i += 256) {
            int r = i >> 3, cc = i & 7;
            u32 soff = (u32)(r*SQK + cc*16);
            cp_async16(sb + OFF_KH + soff, kh16 + i);
            cp_async16(sb + OFF_KL + soff, kl16 + i);
        }
        CP_COMMIT();
    }

    for (int i = tid; i < 2048; i += 256) {
        int r = i >> 4, cc = i & 15;
        u32 off = (u32)(r*SQK + cc*8);

        float4 qv = *(const float4*)(qb + r*64 + cc*4);
        qv.x *= 0.125f; qv.y *= 0.125f; qv.z *= 0.125f; qv.w *= 0.125f;
        u32 qh0 = bf2(qv.x, qv.y), qh1 = bf2(qv.z, qv.w);
        __nv_bfloat162 qhh0 = *(__nv_bfloat162*)&qh0;
        __nv_bfloat162 qhh1 = *(__nv_bfloat162*)&qh1;
        u32 ql0 = bf2(qv.x - __bfloat162float(qhh0.x), qv.y - __bfloat162float(qhh0.y));
        u32 ql1 = bf2(qv.z - __bfloat162float(qhh1.x), qv.w - __bfloat162float(qhh1.y));
        *(u64*)(smc + OFF_QH + off) = ((u64)qh1 << 32) | qh0;
        *(u64*)(smc + OFF_QL + off) = ((u64)ql1 << 32) | ql0;

        float4 vv = *(const float4*)(vb + r*64 + cc*4);
        u32 vh0 = bf2(vv.x, vv.y), vh1 = bf2(vv.z, vv.w);
        __nv_bfloat162 vhh0 = *(__nv_bfloat162*)&vh0;
        __nv_bfloat162 vhh1 = *(__nv_bfloat162*)&vh1;
        u32 vl0 = bf2(vv.x - __bfloat162float(vhh0.x), vv.y - __bfloat162float(vhh0.y));
        u32 vl1 = bf2(vv.z - __bfloat162float(vhh1.x), vv.w - __bfloat162float(vhh1.y));
        *(u64*)(smc + OFF_VH + off) = ((u64)vh1 << 32) | vh0;
        *(u64*)(smc + OFF_VL + off) = ((u64)vl1 << 32) | vl0;
    }
    CP_WAIT0();
    __syncthreads();

    int wm = w & 3, wn = w >> 2;
    float acc[2][8][4];
    #pragma unroll
    for (int mt = 0; mt < 2; mt++)
        #pragma unroll
        for (int nt = 0; nt < 8; nt++)
            #pragma unroll
            for (int e = 0; e < 4; e++) acc[mt][nt][e] = 0.f;

    {
        u32 AbH = sb + OFF_QH + wm*32*SQK;
        u32 AbL = sb + OFF_QL + wm*32*SQK;
        u32 BbH = sb + OFF_KH + wn*64*SQK;
        u32 BbL = sb + OFF_KL + wn*64*SQK;
        #pragma unroll
        for (int ks = 0; ks < 4; ks++) {
            u32 ah[2][4], al[2][4], b[4][4];
            ldmA(ah[0], AbH + ks*32,          SQK, lane);
            ldmA(ah[1], AbH + 16*SQK + ks*32, SQK, lane);
            ldmA(al[0], AbL + ks*32,          SQK, lane);
            ldmA(al[1], AbL + 16*SQK + ks*32, SQK, lane);
            #pragma unroll
            for (int np = 0; np < 4; np++)
                ldmB(b[np], BbH + np*16*SQK + ks*32, SQK, lane);
            #pragma unroll
            for (int mt = 0; mt < 2; mt++)
                #pragma unroll
                for (int nt = 0; nt < 8; nt++)
                    mma16816(acc[mt][nt], ah[mt], &b[nt >> 1][(nt & 1)*2]);
            #pragma unroll
            for (int mt = 0; mt < 2; mt++)
                #pragma unroll
                for (int nt = 0; nt < 8; nt++)
                    mma16816(acc[mt][nt], al[mt], &b[nt >> 1][(nt & 1)*2]);
            #pragma unroll
            for (int np = 0; np < 4; np++)
                ldmB(b[np], BbL + np*16*SQK + ks*32, SQK, lane);
            #pragma unroll
            for (int mt = 0; mt < 2; mt++)
                #pragma unroll
                for (int nt = 0; nt < 8; nt++)
                    mma16816(acc[mt][nt], ah[mt], &b[nt >> 1][(nt & 1)*2]);
        }
    }

    float* sSum = (float*)(smc + OFF_SUM);
    float* sInv = (float*)(smc + OFF_INV);
    int g = lane >> 2, qd = lane & 3;

    #pragma unroll
    for (int mt = 0; mt < 2; mt++) {
        int row = wm*32 + mt*16 + g;
        float e0 = 0.f, e1 = 0.f;
        #pragma unroll
        for (int nt = 0; nt < 8; nt++) {
            acc[mt][nt][0] = __expf(acc[mt][nt][0]);
            acc[mt][nt][1] = __expf(acc[mt][nt][1]);
            acc[mt][nt][2] = __expf(acc[mt][nt][2]);
            acc[mt][nt][3] = __expf(acc[mt][nt][3]);
            e0 += acc[mt][nt][0] + acc[mt][nt][1];
            e1 += acc[mt][nt][2] + acc[mt][nt][3];
        }
        e0 += __shfl_xor_sync(0xffffffffu, e0, 1);
        e0 += __shfl_xor_sync(0xffffffffu, e0, 2);
        e1 += __shfl_xor_sync(0xffffffffu, e1, 1);
        e1 += __shfl_xor_sync(0xffffffffu, e1, 2);
        if (qd == 0) {
            sSum[wn*128 + row]     = e0;
            sSum[wn*128 + row + 8] = e1;
        }
    }
    __syncthreads();

    if (wn == 0 && qd == 0) {
        #pragma unroll
        for (int mt = 0; mt < 2; mt++) {
            int row = wm*32 + mt*16 + g;
            sInv[row]     = 1.0f / (sSum[row]     + sSum[128 + row]);
            sInv[row + 8] = 1.0f / (sSum[row + 8] + sSum[128 + row + 8]);
        }
    }

    u32 AH[2][4][4], AL[2][4][4];
    #pragma unroll
    for (int mt = 0; mt < 2; mt++)
        #pragma unroll
        for (int t = 0; t < 4; t++) {
            #pragma unroll
            for (int hp = 0; hp < 2; hp++) {
                float p0 = acc[mt][2*t+hp][0], p1 = acc[mt][2*t+hp][1];
                float p2 = acc[mt][2*t+hp][2], p3 = acc[mt][2*t+hp][3];
                u32 h01 = bf2(p0, p1), h23 = bf2(p2, p3);
                __nv_bfloat162 hh01 = *(__nv_bfloat162*)&h01;
                __nv_bfloat162 hh23 = *(__nv_bfloat162*)&h23;
                AH[mt][t][2*hp]   = h01;
                AH[mt][t][2*hp+1] = h23;
                AL[mt][t][2*hp]   = bf2(p0 - __bfloat162float(hh01.x),
                                        p1 - __bfloat162float(hh01.y));
                AL[mt][t][2*hp+1] = bf2(p2 - __bfloat162float(hh23.x),
                                        p3 - __bfloat162float(hh23.y));
            }
        }

    u32 bufoff = (wn == 0) ? OFF_BUFA : OFF_BUFB;
    #pragma unroll
    for (int half = 0; half < 2; half++) {
        float o[2][4][4];
        #pragma unroll
        for (int mt = 0; mt < 2; mt++)
            #pragma unroll
            for (int nt = 0; nt < 4; nt++)
                #pragma unroll
                for (int e = 0; e < 4; e++) o[mt][nt][e] = 0.f;

        #pragma unroll
        for (int t = 0; t < 4; t++) {
            u32 vrow = sb + OFF_VH + (wn*64 + t*16)*SV + half*64;
            u32 b[2][4];
            ldmBt(b[0], vrow,      SV, lane);
            ldmBt(b[1], vrow + 32, SV, lane);
            #pragma unroll
            for (int mt = 0; mt < 2; mt++)
                #pragma unroll
                for (int nt = 0; nt < 4; nt++)
                    mma16816(o[mt][nt], AH[mt][t], &b[nt >> 1][(nt & 1)*2]);
            #pragma unroll
            for (int mt = 0; mt < 2; mt++)
                #pragma unroll
                for (int nt = 0; nt < 4; nt++)
                    mma16816(o[mt][nt], AL[mt][t], &b[nt >> 1][(nt & 1)*2]);
            u32 vrl = vrow + (OFF_VL - OFF_VH);
            ldmBt(b[0], vrl,      SV, lane);
            ldmBt(b[1], vrl + 32, SV, lane);
            #pragma unroll
            for (int mt = 0; mt < 2; mt++)
                #pragma unroll
                for (int nt = 0; nt < 4; nt++)
                    mma16816(o[mt][nt], AH[mt][t], &b[nt >> 1][(nt & 1)*2]);
        }

        #pragma unroll
        for (int mt = 0; mt < 2; mt++) {
            int row0 = wm*32 + mt*16 + g;
            #pragma unroll
            for (int nt = 0; nt < 4; nt++) {
                u32 cb = (u32)((half*32 + nt*8 + qd*2) * 4);
                *(float2*)(smc + bufoff + row0*(SRED*4) + cb) =
                    make_float2(o[mt][nt][0], o[mt][nt][1]);
                *(float2*)(smc + bufoff + (row0+8)*(SRED*4) + cb) =
                    make_float2(o[mt][nt][2], o[mt][nt][3]);
            }
        }
    }
    __syncthreads();

    const float* bA = (const float*)(smc + OFF_BUFA);
    const float* bB = (const float*)(smc + OFF_BUFB);
    float* ob = out + base;
    for (int i = tid; i < 2048; i += 256) {
        int r = i >> 4, c4 = i & 15;
        float4 a4 = *(const float4*)(bA + r*SRED + c4*4);
        float4 b4 = *(const float4*)(bB + r*SRED + c4*4);
        float inv = sInv[r];
        float4 res = make_float4((a4.x + b4.x)*inv, (a4.y + b4.y)*inv,
                                 (a4.z + b4.z)*inv, (a4.w + b4.w)*inv);
        *(float4*)(ob + r*64 + c4*4) = res;
    }
}

// ---------------------------------------------------------------------------
extern "C" void kernel_launch(void* const* d_in, const int* in_sizes, int n_in,
                              void* d_out, int out_size) {
    const float* q  = (const float*)d_in[0];
    const float* k  = (const float*)d_in[1];
    const float* v  = (const float*)d_in[2];
    const float* Wk = (const float*)d_in[3];
    float* out = (float*)d_out;

    cudaFuncSetAttribute(k_attn, cudaFuncAttributeMaxDynamicSharedMemorySize, SMEM_TOT);

    k_route_sinkhorn<<<BH, 1024>>>(k, Wk);
    k_kmix          <<<BH*32, 256>>>(k);
    k_attn          <<<BH*NBUCK, 256, SMEM_TOT>>>(q, v, out);
}

// round 17
// speedup vs baseline: 1.0505x; 1.0083x over previous
#include <cuda_runtime.h>
#include <cuda_bf16.h>
#include <cstdint>

#define BH      64
#define NH      16
#define NBUCK   32
#define BSZ     128
#define DIM     64
#define TOK     4096
#define ROW     (TOK*DIM)
#define BUCKF   (BSZ*DIM)

typedef unsigned long long u64;
typedef uint32_t u32;

__device__ float g_pl[BH*NBUCK*DIM];
__device__ float g_R [BH*NBUCK*NBUCK];
__device__ __align__(16) u32 g_kmh[BH*TOK*32];
__device__ __align__(16) u32 g_kml[BH*TOK*32];

// ---- f32x2 helpers ----------------------------------------------------------
__device__ __forceinline__ u64 pack2(float lo, float hi) {
    u64 r; asm("mov.b64 %0,{%1,%2};" : "=l"(r) : "f"(lo), "f"(hi)); return r;
}
__device__ __forceinline__ u64 dup2(float x) {
    u64 r; asm("mov.b64 %0,{%1,%1};" : "=l"(r) : "f"(x)); return r;
}
__device__ __forceinline__ void fma2(u64 &c, u64 a, u64 b) {
    asm("fma.rn.f32x2 %0,%1,%2,%0;" : "+l"(c) : "l"(a), "l"(b));
}
__device__ __forceinline__ float2 unpk(u64 p) {
    float2 f; asm("mov.b64 {%0,%1},%2;" : "=f"(f.x), "=f"(f.y) : "l"(p)); return f;
}

__device__ __forceinline__ u32 smem_u32(const void* p) {
    u32 a; asm("{ .reg .u64 t; cvta.to.shared.u64 t, %1; cvt.u32.u64 %0, t; }"
               : "=r"(a) : "l"(p)); return a;
}
__device__ __forceinline__ u32 bf2(float a, float b) {
    __nv_bfloat162 h = __floats2bfloat162_rn(a, b);
    return *(u32*)&h;
}
__device__ __forceinline__ void cp_async16(u32 saddr, const void* gaddr) {
    asm volatile("cp.async.cg.shared.global [%0], [%1], 16;"
                 :: "r"(saddr), "l"(gaddr) : "memory");
}
#define CP_COMMIT() asm volatile("cp.async.commit_group;" ::: "memory")
#define CP_WAIT0()  asm volatile("cp.async.wait_group 0;" ::: "memory")

// ---- warp MMA helpers -------------------------------------------------------
__device__ __forceinline__ void mma16816(float c[4], const u32 a[4], const u32* b) {
    asm volatile("mma.sync.aligned.m16n8k16.row.col.f32.bf16.bf16.f32 "
        "{%0,%1,%2,%3},{%4,%5,%6,%7},{%8,%9},{%0,%1,%2,%3};"
        : "+f"(c[0]), "+f"(c[1]), "+f"(c[2]), "+f"(c[3])
        : "r"(a[0]), "r"(a[1]), "r"(a[2]), "r"(a[3]), "r"(b[0]), "r"(b[1]));
}
__device__ __forceinline__ void ldmA(u32 a[4], u32 base, int stride, int lane) {
    int r = lane & 7, q = lane >> 3;
    u32 addr = base + (u32)((r + (q & 1) * 8) * stride + (q >> 1) * 16);
    asm volatile("ldmatrix.sync.aligned.m8n8.x4.shared.b16 {%0,%1,%2,%3}, [%4];"
                 : "=r"(a[0]), "=r"(a[1]), "=r"(a[2]), "=r"(a[3]) : "r"(addr));
}
__device__ __forceinline__ void ldmB(u32 b[4], u32 base, int stride, int lane) {
    int r = lane & 7, q = lane >> 3;
    u32 addr = base + (u32)((r + (q >> 1) * 8) * stride + (q & 1) * 16);
    asm volatile("ldmatrix.sync.aligned.m8n8.x4.shared.b16 {%0,%1,%2,%3}, [%4];"
                 : "=r"(b[0]), "=r"(b[1]), "=r"(b[2]), "=r"(b[3]) : "r"(addr));
}
__device__ __forceinline__ void ldmBt(u32 b[4], u32 base, int stride, int lane) {
    int r = lane & 7, q = lane >> 3;
    u32 addr = base + (u32)((r + (q & 1) * 8) * stride + (q >> 1) * 16);
    asm volatile("ldmatrix.sync.aligned.m8n8.x4.trans.shared.b16 {%0,%1,%2,%3}, [%4];"
                 : "=r"(b[0]), "=r"(b[1]), "=r"(b[2]), "=r"(b[3]) : "r"(addr));
}

// ---------------------------------------------------------------------------
// K1: pl[bh][i][d] = sum_s k[...]  (wide: 2048 CTAs, float4, full-chip BW)
// ---------------------------------------------------------------------------
__global__ __launch_bounds__(256) void k_bucket_sum(const float* __restrict__ k) {
    int bid = blockIdx.x;               // 2048
    int bh = bid >> 5, i = bid & 31;
    int t = threadIdx.x, c = t & 15, g = t >> 4;
    const float4* kb4 = (const float4*)(k + (size_t)bh*ROW + (size_t)i*BUCKF);
    float4 s = make_float4(0.f, 0.f, 0.f, 0.f);
    #pragma unroll
    for (int ss = g; ss < BSZ; ss += 16) {
        float4 vv = kb4[ss*16 + c];
        s.x += vv.x; s.y += vv.y; s.z += vv.z; s.w += vv.w;
    }
    __shared__ float4 red[16][16];
    red[g][c] = s;
    __syncthreads();
    if (g == 0) {
        #pragma unroll
        for (int gg = 1; gg < 16; gg++) {
            float4 vv = red[gg][c];
            s.x += vv.x; s.y += vv.y; s.z += vv.z; s.w += vv.w;
        }
        ((float4*)(g_pl + (bh*NBUCK + i)*DIM))[c] = s;
    }
}

// ---------------------------------------------------------------------------
// JAX threefry2x32 (partitionable), key (0,42)
// ---------------------------------------------------------------------------
__device__ __forceinline__ uint32_t rotl32(uint32_t x, int r) {
    return (x << r) | (x >> (32 - r));
}
__device__ __forceinline__ uint32_t jax_bits32(uint32_t n) {
    const uint32_t k0 = 0u, k1 = 42u, k2 = 0u ^ 42u ^ 0x1BD11BDAu;
    uint32_t x0 = k0;
    uint32_t x1 = n + k1;
#define TF_R(r) { x0 += x1; x1 = rotl32(x1, r); x1 ^= x0; }
    TF_R(13) TF_R(15) TF_R(26) TF_R(6)   x0 += k1; x1 += k2 + 1u;
    TF_R(17) TF_R(29) TF_R(16) TF_R(24)  x0 += k2; x1 += k0 + 2u;
    TF_R(13) TF_R(15) TF_R(26) TF_R(6)   x0 += k0; x1 += k1 + 3u;
    TF_R(17) TF_R(29) TF_R(16) TF_R(24)  x0 += k1; x1 += k2 + 4u;
    TF_R(13) TF_R(15) TF_R(26) TF_R(6)   x0 += k2; x1 += k0 + 5u;
#undef TF_R
    return x0 ^ x1;
}

// ---------------------------------------------------------------------------
// K2: routing + gumbel + sinkhorn + exp (reads g_pl; transpose column LSE)
// ---------------------------------------------------------------------------
__global__ __launch_bounds__(1024) void k_route_sinkhorn(const float* __restrict__ Wk) {
    int bh = blockIdx.x;
    int h  = bh & (NH - 1);
    int tid = threadIdx.x;
    int a = tid >> 5, b = tid & 31;

    __shared__ float spl[NBUCK*DIM];
    __shared__ float sW [DIM*NBUCK];
    __shared__ float sT [2][NBUCK*33];

    spl[tid]        = g_pl[bh*(NBUCK*DIM) + tid];
    spl[tid + 1024] = g_pl[bh*(NBUCK*DIM) + tid + 1024];
    sW[tid]         = Wk[h*(DIM*NBUCK) + tid];
    sW[tid + 1024]  = Wk[h*(DIM*NBUCK) + tid + 1024];
    __syncthreads();

    float r = 0.f;
    #pragma unroll
    for (int d = 0; d < DIM; d++) r += spl[a*DIM + d] * sW[d*NBUCK + b];

    uint32_t n = (uint32_t)(bh*1024 + tid);
    uint32_t bits = jax_bits32(n);
    float u = __uint_as_float((bits >> 9) | 0x3f800000u) - 1.0f;
    float g = -logf(-logf(u + 1e-6f) + 1e-6f);
    r = (r + g) / 0.75f;

    for (int it = 0; it < 5; it++) {
        float m = r;
        #pragma unroll
        for (int o = 16; o >= 1; o >>= 1) m = fmaxf(m, __shfl_xor_sync(0xffffffffu, m, o));
        float s = __expf(r - m);
        #pragma unroll
        for (int o = 16; o >= 1; o >>= 1) s += __shfl_xor_sync(0xffffffffu, s, o);
        r = r - (__logf(s) + m);

        sT[0][b*33 + a] = r;
        __syncthreads();
        r = sT[0][a*33 + b];

        m = r;
        #pragma unroll
        for (int o = 16; o >= 1; o >>= 1) m = fmaxf(m, __shfl_xor_sync(0xffffffffu, m, o));
        s = __expf(r - m);
        #pragma unroll
        for (int o = 16; o >= 1; o >>= 1) s += __shfl_xor_sync(0xffffffffu, s, o);
        r = r - (__logf(s) + m);

        sT[1][b*33 + a] = r;
        __syncthreads();
        r = sT[1][a*33 + b];
    }
    g_R[bh*1024 + tid] = __expf(r);
}

// ---------------------------------------------------------------------------
// K3: Kmix = (R+I) @ K — row-split (16 rows/CTA), grid BH*32, 256 threads
// ---------------------------------------------------------------------------
__global__ __launch_bounds__(256) void k_kmix(const float* __restrict__ k) {
    int bid = blockIdx.x;               // 2048
    int bh = bid >> 5, rh = (bid >> 4) & 1, c = bid & 15;
    int row0 = rh * 16;

    int tid = threadIdx.x;

    __shared__ __align__(16) u64 sAT[NBUCK][10];
    for (int idx = tid; idx < NBUCK*8; idx += 256) {
        int j = idx >> 3, p = idx & 7;
        int r0 = row0 + 2*p, r1 = r0 + 1;
        float a0 = g_R[bh*1024 + r0*32 + j] + ((r0 == j) ? 1.0f : 0.0f);
        float a1 = g_R[bh*1024 + r1*32 + j] + ((r1 == j) ? 1.0f : 0.0f);
        sAT[j][p] = pack2(a0, a1);
    }
    __syncthreads();

    const float2* kb2 = (const float2*)(k + (size_t)bh*ROW);
    int col2 = c*256 + tid;
    int t = col2 >> 5, dd = col2 & 31;

    u64 ax[8], ay[8];
    #pragma unroll
    for (int p = 0; p < 8; p++) { ax[p] = 0ull; ay[p] = 0ull; }

    #pragma unroll 4
    for (int j = 0; j < NBUCK; j++) {
        float2 kv = kb2[j*4096 + col2];
        u64 vx = dup2(kv.x), vy = dup2(kv.y);
        #pragma unroll
        for (int p4 = 0; p4 < 4; p4++) {
            ulonglong2 aa = *(const ulonglong2*)&sAT[j][2*p4];
            fma2(ax[2*p4],   aa.x, vx);
            fma2(ax[2*p4+1], aa.y, vx);
            fma2(ay[2*p4],   aa.x, vy);
            fma2(ay[2*p4+1], aa.y, vy);
        }
    }

    size_t ob = (size_t)bh * (TOK*32);
    #pragma unroll
    for (int p = 0; p < 8; p++) {
        float2 fx = unpk(ax[p]);
        float2 fy = unpk(ay[p]);
        int r0 = row0 + 2*p, r1 = r0 + 1;
        __nv_bfloat162 h0 = __floats2bfloat162_rn(fx.x, fy.x);
        __nv_bfloat162 l0 = __floats2bfloat162_rn(fx.x - __bfloat162float(h0.x),
                                                  fy.x - __bfloat162float(h0.y));
        size_t o0 = ob + ((size_t)r0*BSZ + t)*32 + dd;
        g_kmh[o0] = *(u32*)&h0;
        g_kml[o0] = *(u32*)&l0;
        __nv_bfloat162 h1 = __floats2bfloat162_rn(fx.y, fy.y);
        __nv_bfloat162 l1 = __floats2bfloat162_rn(fx.y - __bfloat162float(h1.x),
                                                  fy.y - __bfloat162float(h1.y));
        size_t o1 = ob + ((size_t)r1*BSZ + t)*32 + dd;
        g_kmh[o1] = *(u32*)&h1;
        g_kml[o1] = *(u32*)&l1;
    }
}

// ---------------------------------------------------------------------------
// K4: bucket attention — round-12 best (register-P GEMM2, sInv precompute).
// ---------------------------------------------------------------------------
#define OFF_QH 0
#define OFF_QL 18432
#define OFF_KH 36864
#define OFF_KL 55296
#define OFF_VH 73728
#define OFF_VL 92160
#define OFF_BUFA 0
#define OFF_BUFB 36864
#define OFF_SUM  111616
#define OFF_INV  112640
#define SMEM_TOT 113152
#define SQK 144
#define SV  144
#define SRED 72

__global__ __launch_bounds__(256, 2) void k_attn(const float* __restrict__ q,
                                                 const float* __restrict__ v,
                                                 float* __restrict__ out) {
    extern __shared__ char smc[];
    u32 sb = smem_u32(smc);
    int tid = threadIdx.x, w = tid >> 5, lane = tid & 31;

    size_t base = (size_t)blockIdx.x * BUCKF;
    const float* qb = q + base;
    const float* vb = v + base;

    {
        const uint4* kh16 = (const uint4*)g_kmh + (size_t)blockIdx.x * 1024;
        const uint4* kl16 = (const uint4*)g_kml + (size_t)blockIdx.x * 1024;
        for (int i = tid; i < 1024; i += 256) {
            int r = i >> 3, cc = i & 7;
            u32 soff = (u32)(r*SQK + cc*16);
            cp_async16(sb + OFF_KH + soff, kh16 + i);
            cp_async16(sb + OFF_KL + soff, kl16 + i);
        }
        CP_COMMIT();
    }

    for (int i = tid; i < 2048; i += 256) {
        int r = i >> 4, cc = i & 15;
        u32 off = (u32)(r*SQK + cc*8);

        float4 qv = *(const float4*)(qb + r*64 + cc*4);
        qv.x *= 0.125f; qv.y *= 0.125f; qv.z *= 0.125f; qv.w *= 0.125f;
        u32 qh0 = bf2(qv.x, qv.y), qh1 = bf2(qv.z, qv.w);
        __nv_bfloat162 qhh0 = *(__nv_bfloat162*)&qh0;
        __nv_bfloat162 qhh1 = *(__nv_bfloat162*)&qh1;
        u32 ql0 = bf2(qv.x - __bfloat162float(qhh0.x), qv.y - __bfloat162float(qhh0.y));
        u32 ql1 = bf2(qv.z - __bfloat162float(qhh1.x), qv.w - __bfloat162float(qhh1.y));
        *(u64*)(smc + OFF_QH + off) = ((u64)qh1 << 32) | qh0;
        *(u64*)(smc + OFF_QL + off) = ((u64)ql1 << 32) | ql0;

        float4 vv = *(const float4*)(vb + r*64 + cc*4);
        u32 vh0 = bf2(vv.x, vv.y), vh1 = bf2(vv.z, vv.w);
        __nv_bfloat162 vhh0 = *(__nv_bfloat162*)&vh0;
        __nv_bfloat162 vhh1 = *(__nv_bfloat162*)&vh1;
        u32 vl0 = bf2(vv.x - __bfloat162float(vhh0.x), vv.y - __bfloat162float(vhh0.y));
        u32 vl1 = bf2(vv.z - __bfloat162float(vhh1.x), vv.w - __bfloat162float(vhh1.y));
        *(u64*)(smc + OFF_VH + off) = ((u64)vh1 << 32) | vh0;
        *(u64*)(smc + OFF_VL + off) = ((u64)vl1 << 32) | vl0;
    }
    CP_WAIT0();
    __syncthreads();

    int wm = w & 3, wn = w >> 2;
    float acc[2][8][4];
    #pragma unroll
    for (int mt = 0; mt < 2; mt++)
        #pragma unroll
        for (int nt = 0; nt < 8; nt++)
            #pragma unroll
            for (int e = 0; e < 4; e++) acc[mt][nt][e] = 0.f;

    {
        u32 AbH = sb + OFF_QH + wm*32*SQK;
        u32 AbL = sb + OFF_QL + wm*32*SQK;
        u32 BbH = sb + OFF_KH + wn*64*SQK;
        u32 BbL = sb + OFF_KL + wn*64*SQK;
        #pragma unroll
        for (int ks = 0; ks < 4; ks++) {
            u32 ah[2][4], al[2][4], b[4][4];
            ldmA(ah[0], AbH + ks*32,          SQK, lane);
            ldmA(ah[1], AbH + 16*SQK + ks*32, SQK, lane);
            ldmA(al[0], AbL + ks*32,          SQK, lane);
            ldmA(al[1], AbL + 16*SQK + ks*32, SQK, lane);
            #pragma unroll
            for (int np = 0; np < 4; np++)
                ldmB(b[np], BbH + np*16*SQK + ks*32, SQK, lane);
            #pragma unroll
            for (int mt = 0; mt < 2; mt++)
                #pragma unroll
                for (int nt = 0; nt < 8; nt++)
                    mma16816(acc[mt][nt], ah[mt], &b[nt >> 1][(nt & 1)*2]);
            #pragma unroll
            for (int mt = 0; mt < 2; mt++)
                #pragma unroll
                for (int nt = 0; nt < 8; nt++)
                    mma16816(acc[mt][nt], al[mt], &b[nt >> 1][(nt & 1)*2]);
            #pragma unroll
            for (int np = 0; np < 4; np++)
                ldmB(b[np], BbL + np*16*SQK + ks*32, SQK, lane);
            #pragma unroll
            for (int mt = 0; mt < 2; mt++)
                #pragma unroll
                for (int nt = 0; nt < 8; nt++)
                    mma16816(acc[mt][nt], ah[mt], &b[nt >> 1][(nt & 1)*2]);
        }
    }

    float* sSum = (float*)(smc + OFF_SUM);
    float* sInv = (float*)(smc + OFF_INV);
    int g = lane >> 2, qd = lane & 3;

    #pragma unroll
    for (int mt = 0; mt < 2; mt++) {
        int row = wm*32 + mt*16 + g;
        float e0 = 0.f, e1 = 0.f;
        #pragma unroll
        for (int nt = 0; nt < 8; nt++) {
            acc[mt][nt][0] = __expf(acc[mt][nt][0]);
            acc[mt][nt][1] = __expf(acc[mt][nt][1]);
            acc[mt][nt][2] = __expf(acc[mt][nt][2]);
            acc[mt][nt][3] = __expf(acc[mt][nt][3]);
            e0 += acc[mt][nt][0] + acc[mt][nt][1];
            e1 += acc[mt][nt][2] + acc[mt][nt][3];
        }
        e0 += __shfl_xor_sync(0xffffffffu, e0, 1);
        e0 += __shfl_xor_sync(0xffffffffu, e0, 2);
        e1 += __shfl_xor_sync(0xffffffffu, e1, 1);
        e1 += __shfl_xor_sync(0xffffffffu, e1, 2);
        if (qd == 0) {
            sSum[wn*128 + row]     = e0;
            sSum[wn*128 + row + 8] = e1;
        }
    }
    __syncthreads();

    if (wn == 0 && qd == 0) {
        #pragma unroll
        for (int mt = 0; mt < 2; mt++) {
            int row = wm*32 + mt*16 + g;
            sInv[row]     = 1.0f / (sSum[row]     + sSum[128 + row]);
            sInv[row + 8] = 1.0f / (sSum[row + 8] + sSum[128 + row + 8]);
        }
    }

    u32 AH[2][4][4], AL[2][4][4];
    #pragma unroll
    for (int mt = 0; mt < 2; mt++)
        #pragma unroll
        for (int t = 0; t < 4; t++) {
            #pragma unroll
            for (int hp = 0; hp < 2; hp++) {
                float p0 = acc[mt][2*t+hp][0], p1 = acc[mt][2*t+hp][1];
                float p2 = acc[mt][2*t+hp][2], p3 = acc[mt][2*t+hp][3];
                u32 h01 = bf2(p0, p1), h23 = bf2(p2, p3);
                __nv_bfloat162 hh01 = *(__nv_bfloat162*)&h01;
                __nv_bfloat162 hh23 = *(__nv_bfloat162*)&h23;
                AH[mt][t][2*hp]   = h01;
                AH[mt][t][2*hp+1] = h23;
                AL[mt][t][2*hp]   = bf2(p0 - __bfloat162float(hh01.x),
                                        p1 - __bfloat162float(hh01.y));
                AL[mt][t][2*hp+1] = bf2(p2 - __bfloat162float(hh23.x),
                                        p3 - __bfloat162float(hh23.y));
            }
        }

    u32 bufoff = (wn == 0) ? OFF_BUFA : OFF_BUFB;
    #pragma unroll
    for (int half = 0; half < 2; half++) {
        float o[2][4][4];
        #pragma unroll
        for (int mt = 0; mt < 2; mt++)
            #pragma unroll
            for (int nt = 0; nt < 4; nt++)
                #pragma unroll
                for (int e = 0; e < 4; e++) o[mt][nt][e] = 0.f;

        #pragma unroll
        for (int t = 0; t < 4; t++) {
            u32 vrow = sb + OFF_VH + (wn*64 + t*16)*SV + half*64;
            u32 b[2][4];
            ldmBt(b[0], vrow,      SV, lane);
            ldmBt(b[1], vrow + 32, SV, lane);
            #pragma unroll
            for (int mt = 0; mt < 2; mt++)
                #pragma unroll
                for (int nt = 0; nt < 4; nt++)
                    mma16816(o[mt][nt], AH[mt][t], &b[nt >> 1][(nt & 1)*2]);
            #pragma unroll
            for (int mt = 0; mt < 2; mt++)
                #pragma unroll
                for (int nt = 0; nt < 4; nt++)
                    mma16816(o[mt][nt], AL[mt][t], &b[nt >> 1][(nt & 1)*2]);
            u32 vrl = vrow + (OFF_VL - OFF_VH);
            ldmBt(b[0], vrl,      SV, lane);
            ldmBt(b[1], vrl + 32, SV, lane);
            #pragma unroll
            for (int mt = 0; mt < 2; mt++)
                #pragma unroll
                for (int nt = 0; nt < 4; nt++)
                    mma16816(o[mt][nt], AH[mt][t], &b[nt >> 1][(nt & 1)*2]);
        }

        #pragma unroll
        for (int mt = 0; mt < 2; mt++) {
            int row0 = wm*32 + mt*16 + g;
            #pragma unroll
            for (int nt = 0; nt < 4; nt++) {
                u32 cb = (u32)((half*32 + nt*8 + qd*2) * 4);
                *(float2*)(smc + bufoff + row0*(SRED*4) + cb) =
                    make_float2(o[mt][nt][0], o[mt][nt][1]);
                *(float2*)(smc + bufoff + (row0+8)*(SRED*4) + cb) =
                    make_float2(o[mt][nt][2], o[mt][nt][3]);
            }
        }
    }
    __syncthreads();

    const float* bA = (const float*)(smc + OFF_BUFA);
    const float* bB = (const float*)(smc + OFF_BUFB);
    float* ob = out + base;
    for (int i = tid; i < 2048; i += 256) {
        int r = i >> 4, c4 = i & 15;
        float4 a4 = *(const float4*)(bA + r*SRED + c4*4);
        float4 b4 = *(const float4*)(bB + r*SRED + c4*4);
        float inv = sInv[r];
        float4 res = make_float4((a4.x + b4.x)*inv, (a4.y + b4.y)*inv,
                                 (a4.z + b4.z)*inv, (a4.w + b4.w)*inv);
        *(float4*)(ob + r*64 + c4*4) = res;
    }
}

// ---------------------------------------------------------------------------
extern "C" void kernel_launch(void* const* d_in, const int* in_sizes, int n_in,
                              void* d_out, int out_size) {
    const float* q  = (const float*)d_in[0];
    const float* k  = (const float*)d_in[1];
    const float* v  = (const float*)d_in[2];
    const float* Wk = (const float*)d_in[3];
    float* out = (float*)d_out;

    cudaFuncSetAttribute(k_attn, cudaFuncAttributeMaxDynamicSharedMemorySize, SMEM_TOT);

    k_bucket_sum    <<<BH*NBUCK, 256>>>(k);
    k_route_sinkhorn<<<BH, 1024>>>(Wk);
    k_kmix          <<<BH*32, 256>>>(k);
    k_attn          <<<BH*NBUCK, 256, SMEM_TOT>>>(q, v, out);
}